// round 7
// baseline (speedup 1.0000x reference)
#include <cuda_runtime.h>
#include <cstdint>

#define Bn 64
#define Tn 1024
#define NTh 256
#define NWARP 8
#define NITER 543               // per-warp iterations (2 columns each)
#define NBLK 135                // 135*4 = 540 iters + 3 tail
#define FINF 1000000000.0f
#define ALPHA 0.7f
#define GLN2 0.13862943611198906f      // gamma*ln2
#define SSCALE 2.6857913f              // sqrt(1/(gamma*ln2))
#define SENT 0x7FC00BADu               // NaN pattern; recursion never produces NaN

// dynamic smem: tg[Tn] at 48B stride | edge rings (NWARP+1)*128 f32 | prog[NWARP]
#define TG_BYTES   (Tn * 48)
#define RING_F     ((NWARP + 1) * 128)
#define SMEM_BYTES (TG_BYTES + RING_F * 4 + NWARP * 4)

__device__ float g_mse[Bn * 2 * NWARP];
__device__ float g_r[Bn];
__device__ float g_edge[Bn][Tn];            // row-511 R' values per batch

__device__ __forceinline__ float ex2f(float x) {
    float y; asm("ex2.approx.ftz.f32 %0, %1;" : "=f"(y) : "f"(x)); return y;
}
__device__ __forceinline__ float lg2f(float x) {
    float y; asm("lg2.approx.ftz.f32 %0, %1;" : "=f"(y) : "f"(x)); return y;
}
__device__ __forceinline__ int ld_acq(const int* p) {
    int v; uint32_t a = (uint32_t)__cvta_generic_to_shared(p);
    asm volatile("ld.acquire.cta.shared.b32 %0, [%1];" : "=r"(v) : "r"(a));
    return v;
}
__device__ __forceinline__ void st_rel(int* p, int v) {
    uint32_t a = (uint32_t)__cvta_generic_to_shared(p);
    asm volatile("st.release.cta.shared.b32 [%0], %1;" :: "r"(a), "r"(v));
}
__device__ __forceinline__ float ldcg(const float* p) {
    float v; asm volatile("ld.global.cg.f32 %0, [%1];" : "=f"(v) : "l"(p));
    return v;
}
__device__ __forceinline__ void stcg(float* p, float v) {
    asm volatile("st.global.cg.f32 [%0], %1;" :: "l"(p), "f"(v));
}

// Re-sentinel edge array every launch (inside the graph, same stream).
__global__ void init_kernel() {
    const int i = blockIdx.x * 1024 + threadIdx.x * 4;
    float* p = &g_edge[0][0];
    const float s = __uint_as_float(SENT);
    p[i] = s; p[i + 1] = s; p[i + 2] = s; p[i + 3] = s;
}

// Exact same per-cell softmin as previous rounds (bit-identical).
#define SMIN(up_, lf_, dg_, D_, vld_, out_)                                    \
    { float mn_ = fminf(up_, lf_), mx_ = fmaxf(up_, lf_);                      \
      float v_  = fminf(mn_, dg_), md_ = fmaxf(mn_, dg_);                      \
      float s_  = 1.0f + ex2f(v_ - md_) + ex2f(v_ - mx_);                      \
      out_ = ((D_) + v_) - lg2f(s_);                                           \
      out_ = (vld_) ? out_ : FINF; }

__global__ __launch_bounds__(NTh, 1)
void sdtw_kernel(const float* __restrict__ pred, const float* __restrict__ target)
{
    extern __shared__ char smem[];
    float4* tg       = (float4*)smem;                 // col c -> tg[3c],tg[3c+1],tg[3c+2].x
    float*  edgebase = (float*)(smem + TG_BYTES);     // (NWARP+1) rings of 128
    int*    prog     = (int*)(edgebase + RING_F);

    const int  b    = blockIdx.x >> 1;
    const bool isHi = blockIdx.x & 1;
    const int  t    = threadIdx.x;
    const int  lane = t & 31;
    const int  w    = t >> 5;

    // ---- preprocessing: target (all 1024 rows, 4/thread) ----
    for (int k = 0; k < 4; ++k) {
        const int r = 4 * t + k;
        const float* trow = target + ((size_t)b * Tn + r) * 8;
        float y2 = 0.f, ts[8];
#pragma unroll
        for (int c = 0; c < 8; ++c) {
            float u = trow[c] * SSCALE;
            ts[c] = -2.f * u;
            y2 = fmaf(u, u, y2);
        }
        tg[r * 3 + 0] = make_float4(ts[0], ts[1], ts[2], ts[3]);
        tg[r * 3 + 1] = make_float4(ts[4], ts[5], ts[6], ts[7]);
        tg[r * 3 + 2] = make_float4(y2, 0.f, 0.f, 0.f);
    }
    // pred rows for this CTA (2/thread) + MSE over this half
    const int rbase = (isHi ? 512 : 0) + 2 * t;
    const float* prow = pred   + ((size_t)b * Tn + rbase) * 8;
    const float* urow = target + ((size_t)b * Tn + rbase) * 8;
    float P0[8], P1[8];
    float x20 = 0.f, x21 = 0.f, msep = 0.f;
#pragma unroll
    for (int c = 0; c < 8; ++c) {
        float p0 = prow[c], p1 = prow[8 + c];
        float u0 = urow[c], u1 = urow[8 + c];
        float d0 = p0 - u0, d1 = p1 - u1;
        msep = fmaf(d0, d0, msep); msep = fmaf(d1, d1, msep);
        P0[c] = p0 * SSCALE; P1[c] = p1 * SSCALE;
        x20 = fmaf(P0[c], P0[c], x20);
        x21 = fmaf(P1[c], P1[c], x21);
    }
#pragma unroll
    for (int off = 16; off > 0; off >>= 1)
        msep += __shfl_xor_sync(0xffffffffu, msep, off);
    if (lane == 0) g_mse[(b * 2 + (isHi ? 1 : 0)) * NWARP + w] = msep;

    for (int i = t; i < RING_F; i += NTh) edgebase[i] = FINF;
    if (t < NWARP) prog[t] = 0;
    __syncthreads();                        // the only block barrier

    // ---- warp-systolic wavefront, 2x2 cells per lane per iteration ----
    // Warp w rows [64w, 64w+63]; lane l rows 2l,2l+1 (band-local); iter n:
    // columns c0 = 2n-2l, c1 = c0+1 (skew 2).
    float p0 = FINF, p1 = FINF;            // own rows at col c0-1
    float q0 = FINF, q1 = FINF;            // r1 (row1) at c0, c1 (for shfl down)
    float up_d = (!isHi && w == 0 && lane == 0) ? 0.0f : FINF;  // row-1 at c0-1

    const float* ringP = (w > 0) ? (edgebase + (w - 1) * 128) : (edgebase + NWARP * 128);
    float*       ringW = edgebase + w * 128;
    float*       vring = edgebase + NWARP * 128;
    const bool hasProd = (w > 0);
    const bool hasCons = (w < NWARP - 1);
    const bool gprod   = (!isHi && w == NWARP - 1);   // feeds hi CTA via gmem
    const bool gcons   = (isHi && w == 0);            // consumes gmem edge
    float* gedge = g_edge[b];

#define DTW_ITER(N)                                                            \
  {                                                                            \
    const int c0 = 2 * (N) - 2 * lane;                                         \
    float su0 = __shfl_up_sync(0xffffffffu, q0, 1);                            \
    float su1 = __shfl_up_sync(0xffffffffu, q1, 1);                            \
    float u0, u1;                                                              \
    if (lane == 0) { u0 = ringP[(2 * (N)) & 127];                              \
                     u1 = ringP[(2 * (N) + 1) & 127]; }                        \
    else           { u0 = su0; u1 = su1; }                                     \
    const bool va = ((unsigned)c0 < (unsigned)Tn);                             \
    const bool vb = ((unsigned)(c0 + 1) < (unsigned)Tn);                       \
    const int ja = c0 < 0 ? 0 : (c0 > Tn - 1 ? Tn - 1 : c0);                   \
    const int jb = (c0 + 1) < 0 ? 0 : (c0 + 1 > Tn - 1 ? Tn - 1 : c0 + 1);     \
    float4 gaA = tg[ja * 3], gbA = tg[ja * 3 + 1]; float y2a = tg[ja * 3 + 2].x;\
    float4 gaB = tg[jb * 3], gbB = tg[jb * 3 + 1]; float y2b = tg[jb * 3 + 2].x;\
    float D00 = x20 + y2a, D10 = x21 + y2a;                                    \
    float D01 = x20 + y2b, D11 = x21 + y2b;                                    \
    D00 = fmaf(P0[0], gaA.x, D00); D00 = fmaf(P0[1], gaA.y, D00);              \
    D00 = fmaf(P0[2], gaA.z, D00); D00 = fmaf(P0[3], gaA.w, D00);              \
    D00 = fmaf(P0[4], gbA.x, D00); D00 = fmaf(P0[5], gbA.y, D00);              \
    D00 = fmaf(P0[6], gbA.z, D00); D00 = fmaf(P0[7], gbA.w, D00);              \
    D10 = fmaf(P1[0], gaA.x, D10); D10 = fmaf(P1[1], gaA.y, D10);              \
    D10 = fmaf(P1[2], gaA.z, D10); D10 = fmaf(P1[3], gaA.w, D10);              \
    D10 = fmaf(P1[4], gbA.x, D10); D10 = fmaf(P1[5], gbA.y, D10);              \
    D10 = fmaf(P1[6], gbA.z, D10); D10 = fmaf(P1[7], gbA.w, D10);              \
    D01 = fmaf(P0[0], gaB.x, D01); D01 = fmaf(P0[1], gaB.y, D01);              \
    D01 = fmaf(P0[2], gaB.z, D01); D01 = fmaf(P0[3], gaB.w, D01);              \
    D01 = fmaf(P0[4], gbB.x, D01); D01 = fmaf(P0[5], gbB.y, D01);              \
    D01 = fmaf(P0[6], gbB.z, D01); D01 = fmaf(P0[7], gbB.w, D01);              \
    D11 = fmaf(P1[0], gaB.x, D11); D11 = fmaf(P1[1], gaB.y, D11);              \
    D11 = fmaf(P1[2], gaB.z, D11); D11 = fmaf(P1[3], gaB.w, D11);              \
    D11 = fmaf(P1[4], gbB.x, D11); D11 = fmaf(P1[5], gbB.y, D11);              \
    D11 = fmaf(P1[6], gbB.z, D11); D11 = fmaf(P1[7], gbB.w, D11);              \
    float n00, n01, n10, n11;                                                  \
    SMIN(u0,  p0,  up_d, D00, va, n00)                                         \
    SMIN(u1,  n00, u0,   D01, vb, n01)                                         \
    SMIN(n00, p1,  p0,   D10, va, n10)                                         \
    SMIN(n01, n10, n00,  D11, vb, n11)                                         \
    p0 = n01; p1 = n11; up_d = u1; q0 = n10; q1 = n11;                         \
    if (lane == 31) {                                                          \
      const int cc = 2 * (N) - 62;                                             \
      if ((unsigned)cc < (unsigned)Tn) {                                       \
        ringW[cc & 127] = n10;                                                 \
        if (gprod) stcg(&gedge[cc], n10);                                      \
      }                                                                        \
      if ((unsigned)(cc + 1) < (unsigned)Tn) {                                 \
        ringW[(cc + 1) & 127] = n11;                                           \
        if (gprod) stcg(&gedge[cc + 1], n11);                                  \
      }                                                                        \
    }                                                                          \
  }

    float regv = 0.f;   // gcons prefetch register (lanes 0..7)
    if (gcons) {
        if (lane < 8) {
            float v = ldcg(&gedge[lane]);                    // cols 0..7
            while (__float_as_int(v) == (int)SENT) { __nanosleep(64); v = ldcg(&gedge[lane]); }
            vring[lane] = v;
            regv = ldcg(&gedge[8 + lane]);                   // cols 8..15
        }
        __syncwarp();
    }

    int n = 0;
#pragma unroll 1
    for (int blk = 0; blk < NBLK; ++blk) {
        if (gcons) {
            if (lane < 8) {
                int ci = 2 * n + 8 + lane;                   // insert col
                int cc = ci < Tn - 1 ? ci : Tn - 1;
                while (__float_as_int(regv) == (int)SENT) {  // rare: producer behind
                    __nanosleep(40); regv = ldcg(&gedge[cc]);
                }
                vring[ci & 127] = regv;
                int np = 2 * n + 16 + lane; if (np > Tn - 1) np = Tn - 1;
                regv = ldcg(&gedge[np]);                     // prefetch 16 cols ahead
            }
            __syncwarp();
        } else if (hasProd) {
            int need = n + 35; if (need > NITER) need = NITER;
            while (ld_acq(&prog[w - 1]) < need) __nanosleep(32);
        }
        if (hasCons && n >= 92) {
            int lim = n - 91;
            while (ld_acq(&prog[w + 1]) < lim) __nanosleep(32);
        }
        DTW_ITER(n) DTW_ITER(n + 1) DTW_ITER(n + 2) DTW_ITER(n + 3)
        n += 4;
        st_rel(&prog[w], n);
    }
    // tail: n = 540..542
    {
        if (!gcons && hasProd) {
            while (ld_acq(&prog[w - 1]) < NITER) __nanosleep(32);
        }
        DTW_ITER(540) DTW_ITER(541) DTW_ITER(542)
        st_rel(&prog[w], NITER);
    }
#undef DTW_ITER

    if (isHi && w == NWARP - 1 && lane == 31) g_r[b] = q1;   // R'[1023][1023]
}

__global__ void finalize_kernel(float* out)
{
    __shared__ float sm[256];
    const int t = threadIdx.x;

    float a = 0.f;
    for (int i = t; i < Bn * 2 * NWARP; i += 256) a += g_mse[i];
    sm[t] = a;
    __syncthreads();
#pragma unroll
    for (int s = 128; s > 0; s >>= 1) {
        if (t < s) sm[t] += sm[t + s];
        __syncthreads();
    }
    const float mse_sum = sm[0];
    __syncthreads();

    float r = 0.f;
    for (int i = t; i < Bn; i += 256) r += g_r[i];
    sm[t] = r;
    __syncthreads();
#pragma unroll
    for (int s = 128; s > 0; s >>= 1) {
        if (t < s) sm[t] += sm[t + s];
        __syncthreads();
    }
    if (t == 0) {
        const float mse  = mse_sum / (float)(Bn * Tn * 8);
        const float sdtw = (GLN2 * sm[0]) / (float)Bn;
        out[0] = ALPHA * mse + (1.0f - ALPHA) * sdtw;
    }
}

extern "C" void kernel_launch(void* const* d_in, const int* in_sizes, int n_in,
                              void* d_out, int out_size)
{
    (void)in_sizes; (void)n_in; (void)out_size;
    const float* pred   = (const float*)d_in[0];
    const float* target = (const float*)d_in[1];
    float* out = (float*)d_out;

    cudaFuncSetAttribute(sdtw_kernel,
                         cudaFuncAttributeMaxDynamicSharedMemorySize, SMEM_BYTES);

    init_kernel<<<Bn, 256>>>();
    sdtw_kernel<<<2 * Bn, NTh, SMEM_BYTES>>>(pred, target);
    finalize_kernel<<<1, 256>>>(out);
}

// round 8
// speedup vs baseline: 1.1223x; 1.1223x over previous
#include <cuda_runtime.h>
#include <cstdint>

#define Bn 64
#define Tn 1024
#define NTh 256
#define NWARP 8
#define NITER 543               // per-warp iterations (2 columns each)
#define NBLK 135                // 135*4 = 540 iters + 3 tail
#define FINF 1000000000.0f
#define ALPHA 0.7f
#define GLN2 0.13862943611198906f      // gamma*ln2
#define SSCALE 2.6857913f              // sqrt(1/(gamma*ln2))
#define SENT 0x7FC00BADu               // NaN pattern; recursion never produces NaN

__device__ float g_mse[Bn * 2 * NWARP];
__device__ float g_r[Bn];
__device__ float g_edge[Bn][Tn];            // row-511 R' values per batch

__device__ __forceinline__ float ex2f(float x) {
    float y; asm("ex2.approx.ftz.f32 %0, %1;" : "=f"(y) : "f"(x)); return y;
}
__device__ __forceinline__ float lg2f(float x) {
    float y; asm("lg2.approx.ftz.f32 %0, %1;" : "=f"(y) : "f"(x)); return y;
}
__device__ __forceinline__ int ld_acq(const int* p) {
    int v; uint32_t a = (uint32_t)__cvta_generic_to_shared(p);
    asm volatile("ld.acquire.cta.shared.b32 %0, [%1];" : "=r"(v) : "r"(a));
    return v;
}
__device__ __forceinline__ void st_rel(int* p, int v) {
    uint32_t a = (uint32_t)__cvta_generic_to_shared(p);
    asm volatile("st.release.cta.shared.b32 [%0], %1;" :: "r"(a), "r"(v));
}
__device__ __forceinline__ float ldcg(const float* p) {
    float v; asm volatile("ld.global.cg.f32 %0, [%1];" : "=f"(v) : "l"(p));
    return v;
}
__device__ __forceinline__ void stcg(float* p, float v) {
    asm volatile("st.global.cg.f32 [%0], %1;" :: "l"(p), "f"(v));
}

// Re-sentinel edge array every launch (inside the graph, same stream).
__global__ void init_kernel() {
    const int i = blockIdx.x * 1024 + threadIdx.x * 4;
    float* p = &g_edge[0][0];
    const float s = __uint_as_float(SENT);
    p[i] = s; p[i + 1] = s; p[i + 2] = s; p[i + 3] = s;
}

// Exact same per-cell softmin as R5/R6/R7 (bit-identical).
#define SMIN(up_, lf_, dg_, D_, vld_, out_)                                    \
    { float mn_ = fminf(up_, lf_), mx_ = fmaxf(up_, lf_);                      \
      float v_  = fminf(mn_, dg_), md_ = fmaxf(mn_, dg_);                      \
      float s_  = 1.0f + ex2f(v_ - md_) + ex2f(v_ - mx_);                      \
      out_ = ((D_) + v_) - lg2f(s_);                                           \
      out_ = (vld_) ? out_ : FINF; }

__global__ __launch_bounds__(NTh, 1)
void sdtw_kernel(const float* __restrict__ pred, const float* __restrict__ target)
{
    // Parity-split target tiles: lane accesses index q = n - lane (consecutive)
    // -> conflict-free LDS.128 / LDS.32.
    __shared__ float4 evA[Tn / 2], evB[Tn / 2];   // even cols: -2*s*t[0..3], [4..7]
    __shared__ float4 odA[Tn / 2], odB[Tn / 2];   // odd  cols
    __shared__ float  evY[Tn / 2], odY[Tn / 2];   // s^2*|t|^2
    __shared__ float  rings[(NWARP + 1) * 128];   // per-warp edge rings + virtual ring
    __shared__ int    prog[NWARP];

    const int  b    = blockIdx.x >> 1;
    const bool isHi = blockIdx.x & 1;
    const int  t    = threadIdx.x;
    const int  lane = t & 31;
    const int  w    = t >> 5;

    // ---- preprocessing: target (all 1024 rows, 4/thread) ----
    for (int k = 0; k < 4; ++k) {
        const int r = 4 * t + k;
        const float* trow = target + ((size_t)b * Tn + r) * 8;
        float y2 = 0.f, ts[8];
#pragma unroll
        for (int c = 0; c < 8; ++c) {
            float u = trow[c] * SSCALE;
            ts[c] = -2.f * u;
            y2 = fmaf(u, u, y2);
        }
        const int h = r >> 1;
        if (r & 1) {
            odA[h] = make_float4(ts[0], ts[1], ts[2], ts[3]);
            odB[h] = make_float4(ts[4], ts[5], ts[6], ts[7]);
            odY[h] = y2;
        } else {
            evA[h] = make_float4(ts[0], ts[1], ts[2], ts[3]);
            evB[h] = make_float4(ts[4], ts[5], ts[6], ts[7]);
            evY[h] = y2;
        }
    }
    // pred rows for this CTA (2/thread) + MSE over this half
    const int rbase = (isHi ? 512 : 0) + 2 * t;
    const float* prow = pred   + ((size_t)b * Tn + rbase) * 8;
    const float* urow = target + ((size_t)b * Tn + rbase) * 8;
    float P0[8], P1[8];
    float x20 = 0.f, x21 = 0.f, msep = 0.f;
#pragma unroll
    for (int c = 0; c < 8; ++c) {
        float p0_ = prow[c], p1_ = prow[8 + c];
        float u0_ = urow[c], u1_ = urow[8 + c];
        float d0 = p0_ - u0_, d1 = p1_ - u1_;
        msep = fmaf(d0, d0, msep); msep = fmaf(d1, d1, msep);
        P0[c] = p0_ * SSCALE; P1[c] = p1_ * SSCALE;
        x20 = fmaf(P0[c], P0[c], x20);
        x21 = fmaf(P1[c], P1[c], x21);
    }
#pragma unroll
    for (int off = 16; off > 0; off >>= 1)
        msep += __shfl_xor_sync(0xffffffffu, msep, off);
    if (lane == 0) g_mse[(b * 2 + (isHi ? 1 : 0)) * NWARP + w] = msep;

    for (int i = t; i < (NWARP + 1) * 128; i += NTh) rings[i] = FINF;
    if (t < NWARP) prog[t] = 0;
    __syncthreads();                        // the only block barrier

    // ---- warp-systolic wavefront, 2x2 cells per lane per iteration ----
    float p0 = FINF, p1 = FINF;            // own rows at col c0-1
    float q0 = FINF, q1 = FINF;            // row1 values at c0, c1 (shfl source)
    float up_d = (!isHi && w == 0 && lane == 0) ? 0.0f : FINF;  // row-1 at c0-1

    const float* ringP = (w > 0) ? (rings + (w - 1) * 128) : (rings + NWARP * 128);
    float*       ringW = rings + w * 128;
    float*       vring = rings + NWARP * 128;
    const bool hasProd = (w > 0);
    const bool hasCons = (w < NWARP - 1);
    const bool gprod   = (!isHi && w == NWARP - 1);   // feeds hi CTA via gmem
    const bool gcons   = (isHi && w == 0);            // consumes gmem edge
    float* gedge = g_edge[b];

#define DTW_ITER(N)                                                            \
  {                                                                            \
    const int q = (N) - lane;                                                  \
    float su0 = __shfl_up_sync(0xffffffffu, q0, 1);                            \
    float su1 = __shfl_up_sync(0xffffffffu, q1, 1);                            \
    float u0, u1;                                                              \
    if (lane == 0) { u0 = ringP[(2 * (N)) & 127];                              \
                     u1 = ringP[(2 * (N) + 1) & 127]; }                        \
    else           { u0 = su0; u1 = su1; }                                     \
    const bool vld = ((unsigned)q < (unsigned)(Tn / 2));                       \
    const int  qc  = q < 0 ? 0 : (q > Tn / 2 - 1 ? Tn / 2 - 1 : q);            \
    float4 gaA = evA[qc], gbA = evB[qc]; float y2a = evY[qc];                  \
    float4 gaB = odA[qc], gbB = odB[qc]; float y2b = odY[qc];                  \
    float D00 = x20 + y2a, D10 = x21 + y2a;                                    \
    float D01 = x20 + y2b, D11 = x21 + y2b;                                    \
    D00 = fmaf(P0[0], gaA.x, D00); D00 = fmaf(P0[1], gaA.y, D00);              \
    D00 = fmaf(P0[2], gaA.z, D00); D00 = fmaf(P0[3], gaA.w, D00);              \
    D00 = fmaf(P0[4], gbA.x, D00); D00 = fmaf(P0[5], gbA.y, D00);              \
    D00 = fmaf(P0[6], gbA.z, D00); D00 = fmaf(P0[7], gbA.w, D00);              \
    D10 = fmaf(P1[0], gaA.x, D10); D10 = fmaf(P1[1], gaA.y, D10);              \
    D10 = fmaf(P1[2], gaA.z, D10); D10 = fmaf(P1[3], gaA.w, D10);              \
    D10 = fmaf(P1[4], gbA.x, D10); D10 = fmaf(P1[5], gbA.y, D10);              \
    D10 = fmaf(P1[6], gbA.z, D10); D10 = fmaf(P1[7], gbA.w, D10);              \
    D01 = fmaf(P0[0], gaB.x, D01); D01 = fmaf(P0[1], gaB.y, D01);              \
    D01 = fmaf(P0[2], gaB.z, D01); D01 = fmaf(P0[3], gaB.w, D01);              \
    D01 = fmaf(P0[4], gbB.x, D01); D01 = fmaf(P0[5], gbB.y, D01);              \
    D01 = fmaf(P0[6], gbB.z, D01); D01 = fmaf(P0[7], gbB.w, D01);              \
    D11 = fmaf(P1[0], gaB.x, D11); D11 = fmaf(P1[1], gaB.y, D11);              \
    D11 = fmaf(P1[2], gaB.z, D11); D11 = fmaf(P1[3], gaB.w, D11);              \
    D11 = fmaf(P1[4], gbB.x, D11); D11 = fmaf(P1[5], gbB.y, D11);              \
    D11 = fmaf(P1[6], gbB.z, D11); D11 = fmaf(P1[7], gbB.w, D11);              \
    float n00, n01, n10, n11;                                                  \
    SMIN(u0,  p0,  up_d, D00, vld, n00)                                        \
    SMIN(u1,  n00, u0,   D01, vld, n01)                                        \
    SMIN(n00, p1,  p0,   D10, vld, n10)                                        \
    SMIN(n01, n10, n00,  D11, vld, n11)                                        \
    p0 = n01; p1 = n11; up_d = u1; q0 = n10; q1 = n11;                         \
    if (lane == 31) {                                                          \
      const int cc = 2 * (N) - 62;                                             \
      if ((unsigned)cc < (unsigned)Tn) {                                       \
        ringW[cc & 127] = n10;                                                 \
        ringW[(cc + 1) & 127] = n11;                                           \
        if (gprod) { stcg(&gedge[cc], n10); stcg(&gedge[cc + 1], n11); }       \
      }                                                                        \
    }                                                                          \
  }

    float regv = 0.f;   // gcons prefetch register (lanes 0..7)
    if (gcons) {
        if (lane < 8) {
            float v = ldcg(&gedge[lane]);                    // cols 0..7
            while (__float_as_int(v) == (int)SENT) { __nanosleep(64); v = ldcg(&gedge[lane]); }
            vring[lane] = v;
            regv = ldcg(&gedge[8 + lane]);                   // cols 8..15
        }
        __syncwarp();
    }

    int n = 0;
#pragma unroll 1
    for (int blk = 0; blk < NBLK; ++blk) {
        if (gcons) {
            if (lane < 8) {
                int ci = 2 * n + 8 + lane;                   // insert col
                int cc = ci < Tn - 1 ? ci : Tn - 1;
                while (__float_as_int(regv) == (int)SENT) {  // rare: producer behind
                    __nanosleep(40); regv = ldcg(&gedge[cc]);
                }
                vring[ci & 127] = regv;
                int np = 2 * n + 16 + lane; if (np > Tn - 1) np = Tn - 1;
                regv = ldcg(&gedge[np]);                     // prefetch 16 cols ahead
            }
            __syncwarp();
        } else if (hasProd) {
            int need = n + 35; if (need > NITER) need = NITER;
            while (ld_acq(&prog[w - 1]) < need) __nanosleep(32);
        }
        if (hasCons && n >= 92) {
            int lim = n - 91;
            while (ld_acq(&prog[w + 1]) < lim) __nanosleep(32);
        }
        DTW_ITER(n) DTW_ITER(n + 1) DTW_ITER(n + 2) DTW_ITER(n + 3)
        n += 4;
        st_rel(&prog[w], n);
    }
    // tail: n = 540..542
    {
        if (!gcons && hasProd) {
            while (ld_acq(&prog[w - 1]) < NITER) __nanosleep(32);
        }
        DTW_ITER(540) DTW_ITER(541) DTW_ITER(542)
        st_rel(&prog[w], NITER);
    }
#undef DTW_ITER

    if (isHi && w == NWARP - 1 && lane == 31) g_r[b] = q1;   // R'[1023][1023]
}

__global__ void finalize_kernel(float* out)
{
    __shared__ float sm[256];
    const int t = threadIdx.x;

    float a = 0.f;
    for (int i = t; i < Bn * 2 * NWARP; i += 256) a += g_mse[i];
    sm[t] = a;
    __syncthreads();
#pragma unroll
    for (int s = 128; s > 0; s >>= 1) {
        if (t < s) sm[t] += sm[t + s];
        __syncthreads();
    }
    const float mse_sum = sm[0];
    __syncthreads();

    float r = 0.f;
    for (int i = t; i < Bn; i += 256) r += g_r[i];
    sm[t] = r;
    __syncthreads();
#pragma unroll
    for (int s = 128; s > 0; s >>= 1) {
        if (t < s) sm[t] += sm[t + s];
        __syncthreads();
    }
    if (t == 0) {
        const float mse  = mse_sum / (float)(Bn * Tn * 8);
        const float sdtw = (GLN2 * sm[0]) / (float)Bn;
        out[0] = ALPHA * mse + (1.0f - ALPHA) * sdtw;
    }
}

extern "C" void kernel_launch(void* const* d_in, const int* in_sizes, int n_in,
                              void* d_out, int out_size)
{
    (void)in_sizes; (void)n_in; (void)out_size;
    const float* pred   = (const float*)d_in[0];
    const float* target = (const float*)d_in[1];
    float* out = (float*)d_out;

    init_kernel<<<Bn, 256>>>();
    sdtw_kernel<<<2 * Bn, NTh>>>(pred, target);
    finalize_kernel<<<1, 256>>>(out);
}

// round 16
// speedup vs baseline: 1.3999x; 1.2473x over previous
#include <cuda_runtime.h>
#include <cstdint>

#define Bn 64
#define Tn 1024
#define HROWS 512               // rows per CTA (half batch)
#define NTh 256
#define NWARP 8
#define NLOC (Tn + 31)          // 1055 local iterations per warp
#define FINF 1000000000.0f
#define ALPHA 0.7f
#define GLN2 0.13862943611198906f      // gamma*ln2
#define SSCALE 2.6857913f              // sqrt(1/(gamma*ln2))
#define SENT 0x7FC00BADu               // NaN bit pattern; recursion never produces NaN

__device__ float g_mse[Bn * 2 * NWARP];
__device__ float g_r[Bn];
__device__ float g_edge[Bn][Tn];            // row-511 R' values, per batch

__device__ __forceinline__ float ex2f(float x) {
    float y; asm("ex2.approx.ftz.f32 %0, %1;" : "=f"(y) : "f"(x)); return y;
}
__device__ __forceinline__ float lg2f(float x) {
    float y; asm("lg2.approx.ftz.f32 %0, %1;" : "=f"(y) : "f"(x)); return y;
}
// "memory" clobbers: compiler fence so ring traffic cannot cross the waits.
__device__ __forceinline__ int ld_acq(const int* p) {
    int v; uint32_t a = (uint32_t)__cvta_generic_to_shared(p);
    asm volatile("ld.acquire.cta.shared.b32 %0, [%1];" : "=r"(v) : "r"(a) : "memory");
    return v;
}
__device__ __forceinline__ void st_rel(int* p, int v) {
    uint32_t a = (uint32_t)__cvta_generic_to_shared(p);
    asm volatile("st.release.cta.shared.b32 [%0], %1;" :: "r"(a), "r"(v) : "memory");
}
__device__ __forceinline__ float ldcg(const float* p) {
    float v; asm volatile("ld.global.cg.f32 %0, [%1];" : "=f"(v) : "l"(p) : "memory");
    return v;
}
__device__ __forceinline__ void stcg(float* p, float v) {
    asm volatile("st.global.cg.f32 [%0], %1;" :: "l"(p), "f"(v) : "memory");
}

// Re-sentinel the edge array every launch (runs inside the graph, same stream).
__global__ void init_kernel() {
    const int i = blockIdx.x * 1024 + threadIdx.x * 4;
    float* p = &g_edge[0][0];
    const float s = __uint_as_float(SENT);
    p[i] = s; p[i + 1] = s; p[i + 2] = s; p[i + 3] = s;
}

__global__ __launch_bounds__(NTh, 1)
void sdtw_kernel(const float* __restrict__ pred, const float* __restrict__ target)
{
    __shared__ float4 tgA[Tn];             // -2*SSCALE*target[0..3]
    __shared__ float4 tgB[Tn];             // -2*SSCALE*target[4..7]
    __shared__ float  y2s[Tn];             // SSCALE^2 * |target|^2
    __shared__ float  edge[NWARP + 1][64]; // [w]: warp w ring; [8]: virtual producer ring
    __shared__ int    prog[NWARP];

    const int  b    = blockIdx.x >> 1;
    const bool isHi = blockIdx.x & 1;
    const int  t    = threadIdx.x;
    const int  lane = t & 31;
    const int  w    = t >> 5;

    // ---- preprocessing ----
    for (int k = 0; k < 4; ++k) {
        const int r = 4 * t + k;
        const float* trow = target + ((size_t)b * Tn + r) * 8;
        float y2 = 0.f, ts[8];
#pragma unroll
        for (int c = 0; c < 8; ++c) {
            float u = trow[c] * SSCALE;
            ts[c] = -2.f * u;
            y2 = fmaf(u, u, y2);
        }
        tgA[r] = make_float4(ts[0], ts[1], ts[2], ts[3]);
        tgB[r] = make_float4(ts[4], ts[5], ts[6], ts[7]);
        y2s[r] = y2;
    }
    const int rbase = (isHi ? HROWS : 0) + 2 * t;
    const float* prow = pred   + ((size_t)b * Tn + rbase) * 8;
    const float* urow = target + ((size_t)b * Tn + rbase) * 8;
    float P0[8], P1[8];
    float x20 = 0.f, x21 = 0.f, msep = 0.f;
#pragma unroll
    for (int c = 0; c < 8; ++c) {
        float p0 = prow[c], p1 = prow[8 + c];
        float u0 = urow[c], u1 = urow[8 + c];
        float d0 = p0 - u0, d1 = p1 - u1;
        msep = fmaf(d0, d0, msep); msep = fmaf(d1, d1, msep);
        P0[c] = p0 * SSCALE; P1[c] = p1 * SSCALE;
        x20 = fmaf(P0[c], P0[c], x20);
        x21 = fmaf(P1[c], P1[c], x21);
    }
#pragma unroll
    for (int off = 16; off > 0; off >>= 1)
        msep += __shfl_xor_sync(0xffffffffu, msep, off);
    if (lane == 0) g_mse[(b * 2 + (isHi ? 1 : 0)) * NWARP + w] = msep;

    if (t < 64) edge[NWARP][t] = FINF;     // virtual ring default (lo w0 reads FINF)
    if (t < NWARP) prog[t] = 0;
    __syncthreads();                        // the only block barrier

    // ---- warp-systolic wavefront ----
    float r0 = FINF, r1 = FINF;
    float nbrA = (!isHi && w == 0 && lane == 0) ? 0.0f : FINF;  // (0,0) diag seed
    float nbrB = FINF;

    const float* prodRing = (w > 0) ? edge[w - 1] : edge[NWARP];
    float*       edgeW    = edge[w];
    float*       vring    = edge[NWARP];
    const bool hasProd = (w > 0);
    const bool hasCons = (w < NWARP - 1);
    const bool gprod   = (!isHi && w == NWARP - 1);   // feeds hi CTA via gmem
    const bool gcons   = (isHi && w == 0);            // consumes gmem edge
    float* gedge = g_edge[b];

#define DTW_ITER(N)                                                            \
  {                                                                            \
    float sh = __shfl_up_sync(0xffffffffu, r1, 1);                             \
    float newA = (lane == 0) ? prodRing[((N) + 31) & 63] : sh;                 \
    nbrB = nbrA; nbrA = newA;                                                  \
    int j = (N) - lane;                                                        \
    bool valid = ((unsigned)j < (unsigned)Tn);                                 \
    int jc = valid ? j : 0;                                                    \
    float4 ga = tgA[jc]; float4 gb = tgB[jc]; float y2j = y2s[jc];             \
    float D0 = x20 + y2j, D1 = x21 + y2j;                                      \
    D0 = fmaf(P0[0], ga.x, D0); D0 = fmaf(P0[1], ga.y, D0);                    \
    D0 = fmaf(P0[2], ga.z, D0); D0 = fmaf(P0[3], ga.w, D0);                    \
    D0 = fmaf(P0[4], gb.x, D0); D0 = fmaf(P0[5], gb.y, D0);                    \
    D0 = fmaf(P0[6], gb.z, D0); D0 = fmaf(P0[7], gb.w, D0);                    \
    D1 = fmaf(P1[0], ga.x, D1); D1 = fmaf(P1[1], ga.y, D1);                    \
    D1 = fmaf(P1[2], ga.z, D1); D1 = fmaf(P1[3], ga.w, D1);                    \
    D1 = fmaf(P1[4], gb.x, D1); D1 = fmaf(P1[5], gb.y, D1);                    \
    D1 = fmaf(P1[6], gb.z, D1); D1 = fmaf(P1[7], gb.w, D1);                    \
    float mn  = fminf(nbrA, r0), mx  = fmaxf(nbrA, r0);                        \
    float v0  = fminf(mn, nbrB), md  = fmaxf(mn, nbrB);                        \
    float s0  = 1.0f + ex2f(v0 - md) + ex2f(v0 - mx);                          \
    float r0n = (D0 + v0) - lg2f(s0);                                          \
    r0n = valid ? r0n : FINF;                                                  \
    float mn1 = fminf(r0n, r1), mx1 = fmaxf(r0n, r1);                          \
    float v1  = fminf(mn1, r0), md1 = fmaxf(mn1, r0);                          \
    float s1  = 1.0f + ex2f(v1 - md1) + ex2f(v1 - mx1);                        \
    float r1n = (D1 + v1) - lg2f(s1);                                          \
    r1n = valid ? r1n : FINF;                                                  \
    r0 = r0n; r1 = r1n;                                                        \
    if (lane == 31) edgeW[(N) & 63] = r1n;                                     \
    if (gprod && lane == 31 && (N) >= 31) stcg(&gedge[(N) - 31], r1n);         \
  }

    float regv = 0.f;   // gcons prefetch register (lanes 0..7)
    if (gcons) {
        if (lane < 8) {
            float v = ldcg(&gedge[lane]);           // cols 0..7
            while (__float_as_int(v) == (int)SENT) { __nanosleep(64); v = ldcg(&gedge[lane]); }
            vring[(lane + 31) & 63] = v;
            regv = ldcg(&gedge[8 + lane]);          // cols 8..15 (checked at insertion)
        }
        __syncwarp();
    }

    int n = 0;
#pragma unroll 1
    for (int mb = 0; mb < 131; ++mb) {     // 131*8 = 1048 iters
        if (gcons) {
            if (lane < 8) {
                int ci = n + 8 + lane;                       // insert col (<= 1055)
                int cc = ci < Tn - 1 ? ci : Tn - 1;          // clamped load index
                while (__float_as_int(regv) == (int)SENT) {  // rare: producer behind
                    __nanosleep(40); regv = ldcg(&gedge[cc]);
                }
                vring[(ci + 31) & 63] = regv;
                int np = n + 16 + lane; if (np > Tn - 1) np = Tn - 1;
                regv = ldcg(&gedge[np]);                     // prefetch 16 ahead
            }
            __syncwarp();
        } else if (hasProd) {
            int need = ((n + 7 < Tn - 1) ? (n + 7) : (Tn - 1)) + 32;
            while (ld_acq(&prog[w - 1]) < need) { }          // R14: tight spin
        }
        if (hasCons && n >= 87) {
            int lim = n - 86;
            while (ld_acq(&prog[w + 1]) < lim) { }           // R14: tight spin
        }
        DTW_ITER(n)     DTW_ITER(n + 1) DTW_ITER(n + 2) DTW_ITER(n + 3)
        DTW_ITER(n + 4) DTW_ITER(n + 5) DTW_ITER(n + 6) DTW_ITER(n + 7)
        n += 8;
        st_rel(&prog[w], n);
    }
    // tail: n = 1048..1054 (7 iters)
    {
        if (!gcons && hasProd) {
            while (ld_acq(&prog[w - 1]) < NLOC) { }          // R14: tight spin
        }
        DTW_ITER(n)     DTW_ITER(n + 1) DTW_ITER(n + 2) DTW_ITER(n + 3)
        DTW_ITER(n + 4) DTW_ITER(n + 5) DTW_ITER(n + 6)
        st_rel(&prog[w], NLOC);
    }
#undef DTW_ITER

    if (isHi && w == NWARP - 1 && lane == 31) g_r[b] = r1;   // R'[T-1][T-1]
}

__global__ void finalize_kernel(float* out)
{
    __shared__ float sm[256];
    const int t = threadIdx.x;

    float a = 0.f;
    for (int i = t; i < Bn * 2 * NWARP; i += 256) a += g_mse[i];
    sm[t] = a;
    __syncthreads();
#pragma unroll
    for (int s = 128; s > 0; s >>= 1) {
        if (t < s) sm[t] += sm[t + s];
        __syncthreads();
    }
    const float mse_sum = sm[0];
    __syncthreads();

    float r = 0.f;
    for (int i = t; i < Bn; i += 256) r += g_r[i];
    sm[t] = r;
    __syncthreads();
#pragma unroll
    for (int s = 128; s > 0; s >>= 1) {
        if (t < s) sm[t] += sm[t + s];
        __syncthreads();
    }
    if (t == 0) {
        const float mse  = mse_sum / (float)(Bn * Tn * 8);
        const float sdtw = (GLN2 * sm[0]) / (float)Bn;
        out[0] = ALPHA * mse + (1.0f - ALPHA) * sdtw;
    }
}

extern "C" void kernel_launch(void* const* d_in, const int* in_sizes, int n_in,
                              void* d_out, int out_size)
{
    (void)in_sizes; (void)n_in; (void)out_size;
    const float* pred   = (const float*)d_in[0];
    const float* target = (const float*)d_in[1];
    float* out = (float*)d_out;

    init_kernel<<<Bn, 256>>>();
    sdtw_kernel<<<2 * Bn, NTh>>>(pred, target);
    finalize_kernel<<<1, 256>>>(out);
}